// round 1
// baseline (speedup 1.0000x reference)
#include <cuda_runtime.h>
#include <math.h>

// ---------------- problem constants ----------------
constexpr int Bz = 64, Hh = 56, Wh = 56, Cc = 128;
constexpr int NH = 4, WS = 7, SS = 3, HID = 512, HD = 32;
constexpr int NW = 64, L = 49;                 // windows/image, tokens/window
constexpr int MT = Bz * Hh * Wh;               // 200704 tokens total
constexpr float SCALE = 0.17677669529663687f;  // 32^-0.5

// ---------------- scratch (static device globals; no runtime alloc) --------
__device__ float g_hwin[(size_t)MT * Cc];  // LN1 + shifted window partition
__device__ float g_q[(size_t)MT * Cc];     // [win][head][l][hd]
__device__ float g_k[(size_t)MT * Cc];
__device__ float g_v[(size_t)MT * Cc];
__device__ float g_att[(size_t)MT * Cc];   // attention out, window layout [t][C]
__device__ float g_proj[(size_t)MT * Cc];  // proj out, window layout
__device__ float g_x1[(size_t)MT * Cc];    // post-attn residual, pixel layout
__device__ float g_y[(size_t)MT * Cc];     // LN2 out, pixel layout
__device__ float g_hid[(size_t)MT * HID];  // mlp hidden

// ---------------- helpers ----------------
__device__ __forceinline__ float wsum(float v) {
    #pragma unroll
    for (int o = 16; o; o >>= 1) v += __shfl_xor_sync(0xffffffffu, v, o);
    return v;
}
__device__ __forceinline__ float wmax(float v) {
    #pragma unroll
    for (int o = 16; o; o >>= 1) v = fmaxf(v, __shfl_xor_sync(0xffffffffu, v, o));
    return v;
}

// ---------------- K1: LN1 + cyclic shift + window partition ----------------
// warp per token. output g_hwin[t][C], t = win*49 + l (shifted-window order)
__global__ void k_ln1(const float* __restrict__ x,
                      const float* __restrict__ w, const float* __restrict__ b) {
    int gw = (blockIdx.x * blockDim.x + threadIdx.x) >> 5;
    int lane = threadIdx.x & 31;
    if (gw >= MT) return;
    int t = gw;
    int win = t / L, l = t - win * L;
    int bb = win >> 6, wi = win & 63;
    int wh = wi >> 3, ww = wi & 7;
    int hs = wh * WS + l / WS, ws = ww * WS + l % WS;
    int h0 = hs + SS; if (h0 >= Hh) h0 -= Hh;   // shifted image samples x[(i+SS)%H]
    int w0 = ws + SS; if (w0 >= Wh) w0 -= Wh;
    const float4* row = (const float4*)(x + ((size_t)bb * Hh * Wh + h0 * Wh + w0) * Cc);
    float4 v = row[lane];
    float s  = v.x + v.y + v.z + v.w;
    float s2 = v.x * v.x + v.y * v.y + v.z * v.z + v.w * v.w;
    s = wsum(s); s2 = wsum(s2);
    float mu = s * (1.f / Cc);
    float var = s2 * (1.f / Cc) - mu * mu;
    float rs = rsqrtf(var + 1e-5f);
    int c = lane * 4;
    float4 o;
    o.x = (v.x - mu) * rs * w[c + 0] + b[c + 0];
    o.y = (v.y - mu) * rs * w[c + 1] + b[c + 1];
    o.z = (v.z - mu) * rs * w[c + 2] + b[c + 2];
    o.w = (v.w - mu) * rs * w[c + 3] + b[c + 3];
    ((float4*)(g_hwin + (size_t)t * Cc))[lane] = o;
}

// ---------------- generic tiled GEMM: C[m][n] = A[m][:] . Wt[n][:] + bias[n]
// BM=BN=64, BK=16, 256 threads, 4x4 register tile per thread.
// EPI: 0 = plain store, 1 = GELU(exact), 2 = +R residual, 3 = qkv scatter
template <int EPI>
__global__ void k_gemm(const float* __restrict__ A, const float* __restrict__ Wt,
                       const float* __restrict__ bias, float* __restrict__ Co,
                       const float* __restrict__ R, int N, int K) {
    __shared__ float As[16][64];
    __shared__ float Bs[16][64];
    const int m0 = blockIdx.x * 64, n0 = blockIdx.y * 64;
    const int tid = threadIdx.x;
    const int tx = tid & 15, ty = tid >> 4;
    const int lr = tid >> 2, lk = (tid & 3) * 4;
    float acc[4][4] = {};
    const float* Ap = A + (size_t)(m0 + lr) * K + lk;
    const float* Wp = Wt + (size_t)(n0 + lr) * K + lk;
    for (int k0 = 0; k0 < K; k0 += 16) {
        float4 av = *(const float4*)(Ap + k0);
        float4 bv = *(const float4*)(Wp + k0);
        As[lk + 0][lr] = av.x; As[lk + 1][lr] = av.y;
        As[lk + 2][lr] = av.z; As[lk + 3][lr] = av.w;
        Bs[lk + 0][lr] = bv.x; Bs[lk + 1][lr] = bv.y;
        Bs[lk + 2][lr] = bv.z; Bs[lk + 3][lr] = bv.w;
        __syncthreads();
        #pragma unroll
        for (int kk = 0; kk < 16; kk++) {
            float4 a4 = *(const float4*)&As[kk][ty * 4];
            float4 b4 = *(const float4*)&Bs[kk][tx * 4];
            float ar[4] = {a4.x, a4.y, a4.z, a4.w};
            float br[4] = {b4.x, b4.y, b4.z, b4.w};
            #pragma unroll
            for (int i = 0; i < 4; i++)
                #pragma unroll
                for (int j = 0; j < 4; j++)
                    acc[i][j] = fmaf(ar[i], br[j], acc[i][j]);
        }
        __syncthreads();
    }
    #pragma unroll
    for (int i = 0; i < 4; i++) {
        int m = m0 + ty * 4 + i;
        #pragma unroll
        for (int j = 0; j < 4; j++) {
            int n = n0 + tx * 4 + j;
            float v = acc[i][j] + bias[n];
            if (EPI == 0) {
                Co[(size_t)m * N + n] = v;
            } else if (EPI == 1) {
                Co[(size_t)m * N + n] = 0.5f * v * (1.0f + erff(v * 0.7071067811865475f));
            } else if (EPI == 2) {
                Co[(size_t)m * N + n] = v + R[(size_t)m * N + n];
            } else {  // qkv scatter into [win][head][l][hd]
                int wn = m / L, l = m - wn * L;
                int s = n >> 7, c = n & 127, hd = c >> 5, d = c & 31;
                size_t di = ((size_t)(wn * NH + hd) * L + l) * HD + d;
                if (s == 0)      g_q[di] = v * SCALE;
                else if (s == 1) g_k[di] = v;
                else             g_v[di] = v;
            }
        }
    }
}

// ---------------- K3: windowed attention, one CTA per (window, head) -------
__global__ void k_attn(const float* __restrict__ rel_bias) {
    const int w = blockIdx.x, head = blockIdx.y;
    __shared__ float qs[L * HD];     // [i][d]
    __shared__ float kT[HD * L];     // [d][j]  (transposed: conflict-free dot)
    __shared__ float vs[L * HD];     // [j][d]
    __shared__ float S[L][L];        // row stride 49 (odd) -> conflict-free
    __shared__ int   rg[L];
    const int tid = threadIdx.x;     // 128 threads

    const float* qsrc = g_q + (size_t)(w * NH + head) * L * HD;
    const float* ksrc = g_k + (size_t)(w * NH + head) * L * HD;
    const float* vsrc = g_v + (size_t)(w * NH + head) * L * HD;
    // q, v: vectorized copy (1568 floats = 392 float4)
    for (int i = tid; i < (L * HD) / 4; i += 128) {
        ((float4*)qs)[i] = ((const float4*)qsrc)[i];
        ((float4*)vs)[i] = ((const float4*)vsrc)[i];
    }
    // k: transposed store
    for (int idx = tid; idx < L * HD; idx += 128) {
        int j = idx >> 5, d = idx & 31;
        kT[d * L + j] = ksrc[idx];
    }
    // region ids for shifted-window mask
    if (tid < L) {
        int wi = w & 63;
        int wh = wi >> 3, ww = wi & 7;
        int hs = wh * WS + tid / WS, ws = ww * WS + tid % WS;
        int rh = hs < (Hh - WS) ? 0 : (hs < (Hh - SS) ? 1 : 2);
        int rw = ws < (Wh - WS) ? 0 : (ws < (Wh - SS) ? 1 : 2);
        rg[tid] = rh * 3 + rw;
    }
    __syncthreads();

    // S = qk^T (+bias, +mask)
    for (int idx = tid; idx < L * L; idx += 128) {
        int i = idx / L, j = idx - i * L;
        float s = 0.f;
        #pragma unroll
        for (int d = 0; d < HD; d++) s = fmaf(qs[i * HD + d], kT[d * L + j], s);
        int di = i / WS - j / WS + (WS - 1);
        int dj = i % WS - j % WS + (WS - 1);
        s += rel_bias[(di * (2 * WS - 1) + dj) * NH + head];
        if (rg[i] != rg[j]) s -= 100.f;
        S[i][j] = s;
    }
    __syncthreads();

    // softmax: warp per row
    int warp = tid >> 5, lane = tid & 31;
    for (int i = warp; i < L; i += 4) {
        float m = -1e30f;
        for (int j = lane; j < L; j += 32) m = fmaxf(m, S[i][j]);
        m = wmax(m);
        float sum = 0.f;
        for (int j = lane; j < L; j += 32) {
            float e = __expf(S[i][j] - m);
            S[i][j] = e; sum += e;
        }
        sum = wsum(sum);
        float inv = 1.f / sum;
        for (int j = lane; j < L; j += 32) S[i][j] *= inv;
    }
    __syncthreads();

    // O = P @ V, store into window layout [t][C] at channel head*HD+d
    float* dst = g_att + (size_t)w * L * Cc + head * HD;
    for (int idx = tid; idx < L * HD; idx += 128) {
        int i = idx >> 5, d = idx & 31;
        float o = 0.f;
        #pragma unroll
        for (int j = 0; j < L; j++) o = fmaf(S[i][j], vs[j * HD + d], o);
        dst[(size_t)i * Cc + d] = o;
    }
}

// ---------------- K5: window reverse + unshift + residual + LN2 ------------
__global__ void k_unshift_ln2(const float* __restrict__ x,
                              const float* __restrict__ w2, const float* __restrict__ b2) {
    int gw = (blockIdx.x * blockDim.x + threadIdx.x) >> 5;
    int lane = threadIdx.x & 31;
    if (gw >= MT) return;
    int p = gw;
    int bb = p / (Hh * Wh), pix = p - bb * (Hh * Wh);
    int h = pix / Wh, wc = pix - h * Wh;
    int hs = h - SS; if (hs < 0) hs += Hh;
    int ws = wc - SS; if (ws < 0) ws += Wh;
    int t = (bb * NW + (hs / WS) * 8 + (ws / WS)) * L + (hs % WS) * WS + (ws % WS);
    float4 pv = ((const float4*)(g_proj + (size_t)t * Cc))[lane];
    float4 xv = ((const float4*)(x + (size_t)p * Cc))[lane];
    float4 x1;
    x1.x = xv.x + pv.x; x1.y = xv.y + pv.y; x1.z = xv.z + pv.z; x1.w = xv.w + pv.w;
    ((float4*)(g_x1 + (size_t)p * Cc))[lane] = x1;
    float s  = x1.x + x1.y + x1.z + x1.w;
    float s2 = x1.x * x1.x + x1.y * x1.y + x1.z * x1.z + x1.w * x1.w;
    s = wsum(s); s2 = wsum(s2);
    float mu = s * (1.f / Cc);
    float var = s2 * (1.f / Cc) - mu * mu;
    float rs = rsqrtf(var + 1e-5f);
    int c = lane * 4;
    float4 o;
    o.x = (x1.x - mu) * rs * w2[c + 0] + b2[c + 0];
    o.y = (x1.y - mu) * rs * w2[c + 1] + b2[c + 1];
    o.z = (x1.z - mu) * rs * w2[c + 2] + b2[c + 2];
    o.w = (x1.w - mu) * rs * w2[c + 3] + b2[c + 3];
    ((float4*)(g_y + (size_t)p * Cc))[lane] = o;
}

// ---------------- launch ----------------
extern "C" void kernel_launch(void* const* d_in, const int* in_sizes, int n_in,
                              void* d_out, int out_size) {
    const float* x       = (const float*)d_in[0];
    const float* n1w     = (const float*)d_in[1];
    const float* n1b     = (const float*)d_in[2];
    const float* qkv_w   = (const float*)d_in[3];
    const float* qkv_b   = (const float*)d_in[4];
    const float* proj_w  = (const float*)d_in[5];
    const float* proj_b  = (const float*)d_in[6];
    const float* rel_b   = (const float*)d_in[7];
    const float* n2w     = (const float*)d_in[8];
    const float* n2b     = (const float*)d_in[9];
    const float* fc1_w   = (const float*)d_in[10];
    const float* fc1_b   = (const float*)d_in[11];
    const float* fc2_w   = (const float*)d_in[12];
    const float* fc2_b   = (const float*)d_in[13];
    float* out = (float*)d_out;

    float *p_hwin, *p_att, *p_proj, *p_x1, *p_y, *p_hid;
    cudaGetSymbolAddress((void**)&p_hwin, g_hwin);
    cudaGetSymbolAddress((void**)&p_att,  g_att);
    cudaGetSymbolAddress((void**)&p_proj, g_proj);
    cudaGetSymbolAddress((void**)&p_x1,   g_x1);
    cudaGetSymbolAddress((void**)&p_y,    g_y);
    cudaGetSymbolAddress((void**)&p_hid,  g_hid);

    const int MB = MT / 64;  // 3136 row-tiles

    // 1. LN1 + shift + window partition
    k_ln1<<<MT / 8, 256>>>(x, n1w, n1b);
    // 2. qkv GEMM (N=384) with scatter epilogue
    k_gemm<3><<<dim3(MB, 384 / 64), 256>>>(p_hwin, qkv_w, qkv_b, nullptr, nullptr, 384, Cc);
    // 3. attention per (window, head)
    k_attn<<<dim3(Bz * NW, NH), 128>>>(rel_b);
    // 4. proj GEMM (N=128)
    k_gemm<0><<<dim3(MB, 2), 256>>>(p_att, proj_w, proj_b, p_proj, nullptr, Cc, Cc);
    // 5. reverse shift + residual + LN2
    k_unshift_ln2<<<MT / 8, 256>>>(x, n2w, n2b);
    // 6. fc1 + GELU (N=512)
    k_gemm<1><<<dim3(MB, 8), 256>>>(p_y, fc1_w, fc1_b, p_hid, nullptr, HID, Cc);
    // 7. fc2 + residual (N=128, K=512)
    k_gemm<2><<<dim3(MB, 2), 256>>>(p_hid, fc2_w, fc2_b, out, p_x1, Cc, HID);
}

// round 3
// speedup vs baseline: 2.8750x; 2.8750x over previous
#include <cuda_runtime.h>
#include <cuda_fp16.h>
#include <math.h>
#include <cstdint>

// ---------------- problem constants ----------------
constexpr int Bz = 64, Hh = 56, Wh = 56, Cc = 128;
constexpr int NH = 4, WS = 7, SS = 3, HID = 512, HD = 32;
constexpr int NW = 64, L = 49;
constexpr int MT = Bz * Hh * Wh;               // 200704 tokens
constexpr float SCALE = 0.17677669529663687f;  // 32^-0.5

// ---------------- scratch ----------------
__device__ __half g_hwin[(size_t)MT * Cc];
__device__ __half g_q[(size_t)MT * Cc];      // [win][head][l][hd], q pre-scaled
__device__ __half g_k[(size_t)MT * Cc];
__device__ __half g_v[(size_t)MT * Cc];
__device__ __half g_att[(size_t)MT * Cc];
__device__ __half g_proj[(size_t)MT * Cc];
__device__ float  g_x1[(size_t)MT * Cc];
__device__ __half g_y[(size_t)MT * Cc];
__device__ __half g_hid[(size_t)MT * HID];
__device__ __half g_wqkv[384 * 128];
__device__ __half g_wproj[128 * 128];
__device__ __half g_wfc1[512 * 128];
__device__ __half g_wfc2[128 * 512];

// ---------------- helpers ----------------
__device__ __forceinline__ uint32_t smem_u32(const void* p) {
    uint32_t a;
    asm("{ .reg .u64 t; cvta.to.shared.u64 t, %1; cvt.u32.u64 %0, t; }" : "=r"(a) : "l"(p));
    return a;
}
__device__ __forceinline__ void ldsm4(uint32_t* r, uint32_t addr) {
    asm volatile("ldmatrix.sync.aligned.m8n8.x4.shared.b16 {%0,%1,%2,%3}, [%4];"
        : "=r"(r[0]), "=r"(r[1]), "=r"(r[2]), "=r"(r[3]) : "r"(addr));
}
__device__ __forceinline__ void mma16816(float* c, const uint32_t* a, const uint32_t* b) {
    asm volatile("mma.sync.aligned.m16n8k16.row.col.f32.f16.f16.f32 "
        "{%0,%1,%2,%3}, {%4,%5,%6,%7}, {%8,%9}, {%0,%1,%2,%3};"
        : "+f"(c[0]), "+f"(c[1]), "+f"(c[2]), "+f"(c[3])
        : "r"(a[0]), "r"(a[1]), "r"(a[2]), "r"(a[3]), "r"(b[0]), "r"(b[1]));
}
__device__ __forceinline__ float wsum(float v) {
    #pragma unroll
    for (int o = 16; o; o >>= 1) v += __shfl_xor_sync(0xffffffffu, v, o);
    return v;
}
__device__ __forceinline__ float wmax(float v) {
    #pragma unroll
    for (int o = 16; o; o >>= 1) v = fmaxf(v, __shfl_xor_sync(0xffffffffu, v, o));
    return v;
}

// ---------------- K0: weights fp32 -> fp16 ----------------
__global__ void k_cvt(const float* __restrict__ wq, const float* __restrict__ wp,
                      const float* __restrict__ w1, const float* __restrict__ w2) {
    int i = blockIdx.x * 256 + threadIdx.x;  // 65536 threads
    if (i < 49152) g_wqkv[i] = __float2half_rn(wq[i]);
    if (i < 16384) g_wproj[i] = __float2half_rn(wp[i]);
    g_wfc1[i] = __float2half_rn(w1[i]);
    g_wfc2[i] = __float2half_rn(w2[i]);
}

// ---------------- K1: LN1 + cyclic shift + window partition ----------------
__global__ void k_ln1(const float* __restrict__ x,
                      const float* __restrict__ w, const float* __restrict__ b) {
    int gw = (blockIdx.x * blockDim.x + threadIdx.x) >> 5;
    int lane = threadIdx.x & 31;
    if (gw >= MT) return;
    int t = gw;
    int win = t / L, l = t - win * L;
    int bb = win >> 6, wi = win & 63;
    int wh = wi >> 3, ww = wi & 7;
    int hs = wh * WS + l / WS, ws = ww * WS + l % WS;
    int h0 = hs + SS; if (h0 >= Hh) h0 -= Hh;
    int w0 = ws + SS; if (w0 >= Wh) w0 -= Wh;
    const float4* row = (const float4*)(x + ((size_t)bb * Hh * Wh + h0 * Wh + w0) * Cc);
    float4 v = row[lane];
    float s  = v.x + v.y + v.z + v.w;
    float s2 = v.x * v.x + v.y * v.y + v.z * v.z + v.w * v.w;
    s = wsum(s); s2 = wsum(s2);
    float mu = s * (1.f / Cc);
    float var = s2 * (1.f / Cc) - mu * mu;
    float rs = rsqrtf(var + 1e-5f);
    int c = lane * 4;
    float ox = (v.x - mu) * rs * w[c + 0] + b[c + 0];
    float oy = (v.y - mu) * rs * w[c + 1] + b[c + 1];
    float oz = (v.z - mu) * rs * w[c + 2] + b[c + 2];
    float ow = (v.w - mu) * rs * w[c + 3] + b[c + 3];
    __half2* orow = (__half2*)(g_hwin + (size_t)t * Cc);
    orow[lane * 2]     = __floats2half2_rn(ox, oy);
    orow[lane * 2 + 1] = __floats2half2_rn(oz, ow);
}

// ---------------- HMMA GEMM: D[m][n] = A[m][:] . W[n][:] + bias ------------
// CTA 128x128 tile; 8 warps (4 m-rows x 2 n-cols), warp tile 32x64,
// mma.m16n8k16 fp16 -> fp32. A,W fp16 K-major. K in 128-blocks.
// EPI: 0=proj(fp16), 1=fc1 gelu(fp16), 2=fc2 +R (fp32 out), 3=qkv scatter
constexpr int LDS = 136;  // padded smem stride (halves): 272B rows
template <int NTOT, int KTOT, int EPI>
__global__ void __launch_bounds__(256, 2) k_hmma(
    const __half* __restrict__ A, const __half* __restrict__ Wp,
    const float* __restrict__ bias, const float* __restrict__ R,
    float* __restrict__ Co) {
    extern __shared__ __align__(16) __half sm[];
    __half* sA = sm;
    __half* sW = sm + 128 * LDS;
    const uint32_t sAu = smem_u32(sA), sWu = smem_u32(sW);
    const int tid = threadIdx.x, wid = tid >> 5, lane = tid & 31;
    const int wm = wid & 3, wn = wid >> 2;   // warp tile (wm*32, wn*64)
    const int m0 = blockIdx.x * 128, n0 = blockIdx.y * 128;

    float acc[2][8][4];
    #pragma unroll
    for (int i = 0; i < 2; i++)
        #pragma unroll
        for (int j = 0; j < 8; j++)
            #pragma unroll
            for (int k = 0; k < 4; k++) acc[i][j][k] = 0.f;

    // ldmatrix lane addressing (byte offsets into padded tiles)
    const uint32_t aRow = lane & 15, aCg = (lane >> 4) << 3;        // A: 16 rows x 16 cols
    const uint32_t bRow = (lane & 7) + ((lane >> 4) << 3);          // B: n row
    const uint32_t bCg = ((lane >> 3) & 1) << 3;                    // B: k granule

    for (int kb = 0; kb < KTOT / 128; kb++) {
        // stage A tile (128 x 128 halves)
        const __half* Ab = A + (size_t)m0 * KTOT + kb * 128;
        #pragma unroll
        for (int i = tid; i < 128 * 16; i += 256) {
            int r = i >> 4, g = i & 15;
            uint4 v = *(const uint4*)(Ab + (size_t)r * KTOT + g * 8);
            *(uint4*)(sA + r * LDS + g * 8) = v;
        }
        // stage W tile (128 x 128 halves)
        const __half* Wb = Wp + (size_t)n0 * KTOT + kb * 128;
        #pragma unroll
        for (int i = tid; i < 128 * 16; i += 256) {
            int r = i >> 4, g = i & 15;
            uint4 v = *(const uint4*)(Wb + (size_t)r * KTOT + g * 8);
            *(uint4*)(sW + r * LDS + g * 8) = v;
        }
        __syncthreads();

        #pragma unroll
        for (int ks = 0; ks < 8; ks++) {
            const int k0 = ks * 16;
            uint32_t afr[2][4];
            #pragma unroll
            for (int mi = 0; mi < 2; mi++) {
                uint32_t addr = sAu + ((wm * 32 + mi * 16 + aRow) * LDS + k0 + aCg) * 2;
                ldsm4(afr[mi], addr);
            }
            uint32_t bfr[8][2];
            #pragma unroll
            for (int nb = 0; nb < 4; nb++) {
                uint32_t addr = sWu + ((wn * 64 + nb * 16 + bRow) * LDS + k0 + bCg) * 2;
                uint32_t t4[4];
                ldsm4(t4, addr);
                bfr[2 * nb][0] = t4[0]; bfr[2 * nb][1] = t4[1];
                bfr[2 * nb + 1][0] = t4[2]; bfr[2 * nb + 1][1] = t4[3];
            }
            #pragma unroll
            for (int mi = 0; mi < 2; mi++)
                #pragma unroll
                for (int ni = 0; ni < 8; ni++)
                    mma16816(acc[mi][ni], afr[mi], bfr[ni]);
        }
        __syncthreads();
    }

    // ---- epilogue ----
    const int lr = lane >> 2, lc = (lane & 3) * 2;
    #pragma unroll
    for (int mi = 0; mi < 2; mi++) {
        #pragma unroll
        for (int rr = 0; rr < 2; rr++) {
            const int row = m0 + wm * 32 + mi * 16 + rr * 8 + lr;
            int win, lloc;
            if (EPI == 3) { win = row / L; lloc = row - win * L; }
            #pragma unroll
            for (int ni = 0; ni < 8; ni++) {
                const int col = n0 + wn * 64 + ni * 8 + lc;
                float v0 = acc[mi][ni][rr * 2 + 0] + __ldg(bias + col);
                float v1 = acc[mi][ni][rr * 2 + 1] + __ldg(bias + col + 1);
                if (EPI == 3) {
                    int s = col >> 7, c = col & 127, head = c >> 5, d = c & 31;
                    __half* dst = (s == 0 ? g_q : (s == 1 ? g_k : g_v)) +
                                  ((size_t)(win * NH + head) * L + lloc) * HD + d;
                    if (s == 0) { v0 *= SCALE; v1 *= SCALE; }
                    *(__half2*)dst = __floats2half2_rn(v0, v1);
                } else if (EPI == 0) {
                    *(__half2*)(g_proj + (size_t)row * Cc + col) = __floats2half2_rn(v0, v1);
                } else if (EPI == 1) {
                    float gg0 = 0.5f * v0 * (1.0f + erff(v0 * 0.7071067811865475f));
                    float gg1 = 0.5f * v1 * (1.0f + erff(v1 * 0.7071067811865475f));
                    *(__half2*)(g_hid + (size_t)row * HID + col) = __floats2half2_rn(gg0, gg1);
                } else {
                    const float2 rv = *(const float2*)(R + (size_t)row * Cc + col);
                    float2 ov; ov.x = v0 + rv.x; ov.y = v1 + rv.y;
                    *(float2*)(Co + (size_t)row * Cc + col) = ov;
                }
            }
        }
    }
}

// ---------------- K3: windowed attention (fp16 io, fp32 math) --------------
__global__ void k_attn(const float* __restrict__ rel_bias) {
    const int w = blockIdx.x, head = blockIdx.y;
    __shared__ float qs[L * HD];
    __shared__ float kT[HD * L];
    __shared__ float vs[L * HD];
    __shared__ float S[L][L];
    __shared__ int   rg[L];
    const int tid = threadIdx.x;  // 128

    const __half* qsrc = g_q + (size_t)(w * NH + head) * L * HD;
    const __half* ksrc = g_k + (size_t)(w * NH + head) * L * HD;
    const __half* vsrc = g_v + (size_t)(w * NH + head) * L * HD;
    for (int i = tid; i < (L * HD) / 2; i += 128) {
        float2 f = __half22float2(((const __half2*)qsrc)[i]);
        qs[2 * i] = f.x; qs[2 * i + 1] = f.y;
        float2 g = __half22float2(((const __half2*)vsrc)[i]);
        vs[2 * i] = g.x; vs[2 * i + 1] = g.y;
    }
    for (int idx = tid; idx < L * HD; idx += 128) {
        int j = idx >> 5, d = idx & 31;
        kT[d * L + j] = __half2float(ksrc[idx]);
    }
    if (tid < L) {
        int wi = w & 63;
        int wh = wi >> 3, ww = wi & 7;
        int hs = wh * WS + tid / WS, ws = ww * WS + tid % WS;
        int rh = hs < (Hh - WS) ? 0 : (hs < (Hh - SS) ? 1 : 2);
        int rw = ws < (Wh - WS) ? 0 : (ws < (Wh - SS) ? 1 : 2);
        rg[tid] = rh * 3 + rw;
    }
    __syncthreads();

    for (int idx = tid; idx < L * L; idx += 128) {
        int i = idx / L, j = idx - i * L;
        float s = 0.f;
        #pragma unroll
        for (int d = 0; d < HD; d++) s = fmaf(qs[i * HD + d], kT[d * L + j], s);
        int di = i / WS - j / WS + (WS - 1);
        int dj = i % WS - j % WS + (WS - 1);
        s += rel_bias[(di * (2 * WS - 1) + dj) * NH + head];
        if (rg[i] != rg[j]) s -= 100.f;
        S[i][j] = s;
    }
    __syncthreads();

    int warp = tid >> 5, lane = tid & 31;
    for (int i = warp; i < L; i += 4) {
        float m = -1e30f;
        for (int j = lane; j < L; j += 32) m = fmaxf(m, S[i][j]);
        m = wmax(m);
        float sum = 0.f;
        for (int j = lane; j < L; j += 32) {
            float e = __expf(S[i][j] - m);
            S[i][j] = e; sum += e;
        }
        sum = wsum(sum);
        float inv = 1.f / sum;
        for (int j = lane; j < L; j += 32) S[i][j] *= inv;
    }
    __syncthreads();

    __half* dst = g_att + (size_t)w * L * Cc + head * HD;
    for (int idx = tid; idx < L * HD; idx += 128) {
        int i = idx >> 5, d = idx & 31;
        float o = 0.f;
        #pragma unroll
        for (int j = 0; j < L; j++) o = fmaf(S[i][j], vs[j * HD + d], o);
        dst[(size_t)i * Cc + d] = __float2half_rn(o);
    }
}

// ---------------- K5: window reverse + unshift + residual + LN2 ------------
__global__ void k_unshift_ln2(const float* __restrict__ x,
                              const float* __restrict__ w2, const float* __restrict__ b2) {
    int gw = (blockIdx.x * blockDim.x + threadIdx.x) >> 5;
    int lane = threadIdx.x & 31;
    if (gw >= MT) return;
    int p = gw;
    int bb = p / (Hh * Wh), pix = p - bb * (Hh * Wh);
    int h = pix / Wh, wc = pix - h * Wh;
    int hs = h - SS; if (hs < 0) hs += Hh;
    int ws = wc - SS; if (ws < 0) ws += Wh;
    int t = (bb * NW + (hs / WS) * 8 + (ws / WS)) * L + (hs % WS) * WS + (ws % WS);
    const __half2* pr = (const __half2*)(g_proj + (size_t)t * Cc);
    float2 p0 = __half22float2(pr[lane * 2]);
    float2 p1 = __half22float2(pr[lane * 2 + 1]);
    float4 xv = ((const float4*)(x + (size_t)p * Cc))[lane];
    float4 x1;
    x1.x = xv.x + p0.x; x1.y = xv.y + p0.y; x1.z = xv.z + p1.x; x1.w = xv.w + p1.y;
    ((float4*)(g_x1 + (size_t)p * Cc))[lane] = x1;
    float s  = x1.x + x1.y + x1.z + x1.w;
    float s2 = x1.x * x1.x + x1.y * x1.y + x1.z * x1.z + x1.w * x1.w;
    s = wsum(s); s2 = wsum(s2);
    float mu = s * (1.f / Cc);
    float var = s2 * (1.f / Cc) - mu * mu;
    float rs = rsqrtf(var + 1e-5f);
    int c = lane * 4;
    float ox = (x1.x - mu) * rs * w2[c + 0] + b2[c + 0];
    float oy = (x1.y - mu) * rs * w2[c + 1] + b2[c + 1];
    float oz = (x1.z - mu) * rs * w2[c + 2] + b2[c + 2];
    float ow = (x1.w - mu) * rs * w2[c + 3] + b2[c + 3];
    __half2* orow = (__half2*)(g_y + (size_t)p * Cc);
    orow[lane * 2]     = __floats2half2_rn(ox, oy);
    orow[lane * 2 + 1] = __floats2half2_rn(oz, ow);
}

// ---------------- launch ----------------
extern "C" void kernel_launch(void* const* d_in, const int* in_sizes, int n_in,
                              void* d_out, int out_size) {
    const float* x      = (const float*)d_in[0];
    const float* n1w    = (const float*)d_in[1];
    const float* n1b    = (const float*)d_in[2];
    const float* qkv_w  = (const float*)d_in[3];
    const float* qkv_b  = (const float*)d_in[4];
    const float* proj_w = (const float*)d_in[5];
    const float* proj_b = (const float*)d_in[6];
    const float* rel_b  = (const float*)d_in[7];
    const float* n2w    = (const float*)d_in[8];
    const float* n2b    = (const float*)d_in[9];
    const float* fc1_w  = (const float*)d_in[10];
    const float* fc1_b  = (const float*)d_in[11];
    const float* fc2_w  = (const float*)d_in[12];
    const float* fc2_b  = (const float*)d_in[13];
    float* out = (float*)d_out;

    __half *p_hwin, *p_att, *p_y, *p_hid, *p_wqkv, *p_wproj, *p_wfc1, *p_wfc2;
    float* p_x1;
    cudaGetSymbolAddress((void**)&p_hwin, g_hwin);
    cudaGetSymbolAddress((void**)&p_att,  g_att);
    cudaGetSymbolAddress((void**)&p_y,    g_y);
    cudaGetSymbolAddress((void**)&p_hid,  g_hid);
    cudaGetSymbolAddress((void**)&p_x1,   g_x1);
    cudaGetSymbolAddress((void**)&p_wqkv, g_wqkv);
    cudaGetSymbolAddress((void**)&p_wproj, g_wproj);
    cudaGetSymbolAddress((void**)&p_wfc1, g_wfc1);
    cudaGetSymbolAddress((void**)&p_wfc2, g_wfc2);

    constexpr int SMB = 2 * 128 * LDS * 2;  // 69632 bytes
    cudaFuncSetAttribute(k_hmma<384, 128, 3>, cudaFuncAttributeMaxDynamicSharedMemorySize, SMB);
    cudaFuncSetAttribute(k_hmma<128, 128, 0>, cudaFuncAttributeMaxDynamicSharedMemorySize, SMB);
    cudaFuncSetAttribute(k_hmma<512, 128, 1>, cudaFuncAttributeMaxDynamicSharedMemorySize, SMB);
    cudaFuncSetAttribute(k_hmma<128, 512, 2>, cudaFuncAttributeMaxDynamicSharedMemorySize, SMB);

    const int GM = MT / 128;  // 1568 M-tiles

    k_cvt<<<256, 256>>>(qkv_w, proj_w, fc1_w, fc2_w);
    k_ln1<<<MT / 8, 256>>>(x, n1w, n1b);
    k_hmma<384, 128, 3><<<dim3(GM, 3), 256, SMB>>>(p_hwin, p_wqkv, qkv_b, nullptr, nullptr);
    k_attn<<<dim3(Bz * NW, NH), 128>>>(rel_b);
    k_hmma<128, 128, 0><<<dim3(GM, 1), 256, SMB>>>(p_att, p_wproj, proj_b, nullptr, nullptr);
    k_unshift_ln2<<<MT / 8, 256>>>(x, n2w, n2b);
    k_hmma<512, 128, 1><<<dim3(GM, 4), 256, SMB>>>(p_y, p_wfc1, fc1_b, nullptr, nullptr);
    k_hmma<128, 512, 2><<<dim3(GM, 1), 256, SMB>>>(p_hid, p_wfc2, fc2_b, p_x1, out);
}

// round 4
// speedup vs baseline: 5.1706x; 1.7985x over previous
#include <cuda_runtime.h>
#include <cuda_fp16.h>
#include <math.h>
#include <cstdint>

// ---------------- problem constants ----------------
constexpr int Bz = 64, Hh = 56, Wh = 56, Cc = 128;
constexpr int NH = 4, WS = 7, SS = 3, HID = 512, HD = 32;
constexpr int NW = 64, L = 49;
constexpr int MT = Bz * Hh * Wh;               // 200704 tokens
constexpr float SCALE = 0.17677669529663687f;  // 32^-0.5

// ---------------- scratch ----------------
__device__ __half g_hwin[(size_t)MT * Cc];
__device__ __half g_q[(size_t)MT * Cc];      // [win][head][l][hd], q pre-scaled
__device__ __half g_k[(size_t)MT * Cc];
__device__ __half g_v[(size_t)MT * Cc];
__device__ __half g_att[(size_t)MT * Cc];
__device__ __half g_proj[(size_t)MT * Cc];
__device__ float  g_x1[(size_t)MT * Cc];
__device__ __half g_y[(size_t)MT * Cc];
__device__ __half g_hid[(size_t)MT * HID];
__device__ __half g_wqkv[384 * 128];
__device__ __half g_wproj[128 * 128];
__device__ __half g_wfc1[512 * 128];
__device__ __half g_wfc2[128 * 512];

// ---------------- helpers ----------------
__device__ __forceinline__ uint32_t smem_u32(const void* p) {
    uint32_t a;
    asm("{ .reg .u64 t; cvta.to.shared.u64 t, %1; cvt.u32.u64 %0, t; }" : "=r"(a) : "l"(p));
    return a;
}
__device__ __forceinline__ void ldsm4(uint32_t* r, uint32_t addr) {
    asm volatile("ldmatrix.sync.aligned.m8n8.x4.shared.b16 {%0,%1,%2,%3}, [%4];"
        : "=r"(r[0]), "=r"(r[1]), "=r"(r[2]), "=r"(r[3]) : "r"(addr));
}
__device__ __forceinline__ void mma16816(float* c, const uint32_t* a, const uint32_t* b) {
    asm volatile("mma.sync.aligned.m16n8k16.row.col.f32.f16.f16.f32 "
        "{%0,%1,%2,%3}, {%4,%5,%6,%7}, {%8,%9}, {%0,%1,%2,%3};"
        : "+f"(c[0]), "+f"(c[1]), "+f"(c[2]), "+f"(c[3])
        : "r"(a[0]), "r"(a[1]), "r"(a[2]), "r"(a[3]), "r"(b[0]), "r"(b[1]));
}
__device__ __forceinline__ float wsum(float v) {
    #pragma unroll
    for (int o = 16; o; o >>= 1) v += __shfl_xor_sync(0xffffffffu, v, o);
    return v;
}
__device__ __forceinline__ float wmax(float v) {
    #pragma unroll
    for (int o = 16; o; o >>= 1) v = fmaxf(v, __shfl_xor_sync(0xffffffffu, v, o));
    return v;
}

// ---------------- K0: weights fp32 -> fp16 ----------------
__global__ void k_cvt(const float* __restrict__ wq, const float* __restrict__ wp,
                      const float* __restrict__ w1, const float* __restrict__ w2) {
    int i = blockIdx.x * 256 + threadIdx.x;  // 65536 threads
    if (i < 49152) g_wqkv[i] = __float2half_rn(wq[i]);
    if (i < 16384) g_wproj[i] = __float2half_rn(wp[i]);
    g_wfc1[i] = __float2half_rn(w1[i]);
    g_wfc2[i] = __float2half_rn(w2[i]);
}

// ---------------- K1: LN1 + cyclic shift + window partition ----------------
__global__ void k_ln1(const float* __restrict__ x,
                      const float* __restrict__ w, const float* __restrict__ b) {
    int gw = (blockIdx.x * blockDim.x + threadIdx.x) >> 5;
    int lane = threadIdx.x & 31;
    if (gw >= MT) return;
    int t = gw;
    int win = t / L, l = t - win * L;
    int bb = win >> 6, wi = win & 63;
    int wh = wi >> 3, ww = wi & 7;
    int hs = wh * WS + l / WS, ws = ww * WS + l % WS;
    int h0 = hs + SS; if (h0 >= Hh) h0 -= Hh;
    int w0 = ws + SS; if (w0 >= Wh) w0 -= Wh;
    const float4* row = (const float4*)(x + ((size_t)bb * Hh * Wh + h0 * Wh + w0) * Cc);
    float4 v = row[lane];
    float s  = v.x + v.y + v.z + v.w;
    float s2 = v.x * v.x + v.y * v.y + v.z * v.z + v.w * v.w;
    s = wsum(s); s2 = wsum(s2);
    float mu = s * (1.f / Cc);
    float var = s2 * (1.f / Cc) - mu * mu;
    float rs = rsqrtf(var + 1e-5f);
    int c = lane * 4;
    float ox = (v.x - mu) * rs * w[c + 0] + b[c + 0];
    float oy = (v.y - mu) * rs * w[c + 1] + b[c + 1];
    float oz = (v.z - mu) * rs * w[c + 2] + b[c + 2];
    float ow = (v.w - mu) * rs * w[c + 3] + b[c + 3];
    __half2* orow = (__half2*)(g_hwin + (size_t)t * Cc);
    orow[lane * 2]     = __floats2half2_rn(ox, oy);
    orow[lane * 2 + 1] = __floats2half2_rn(oz, ow);
}

// ---------------- HMMA GEMM (unchanged from round 3) -----------------------
constexpr int LDS = 136;
template <int NTOT, int KTOT, int EPI>
__global__ void __launch_bounds__(256, 2) k_hmma(
    const __half* __restrict__ A, const __half* __restrict__ Wp,
    const float* __restrict__ bias, const float* __restrict__ R,
    float* __restrict__ Co) {
    extern __shared__ __align__(16) __half sm[];
    __half* sA = sm;
    __half* sW = sm + 128 * LDS;
    const uint32_t sAu = smem_u32(sA), sWu = smem_u32(sW);
    const int tid = threadIdx.x, wid = tid >> 5, lane = tid & 31;
    const int wm = wid & 3, wn = wid >> 2;
    const int m0 = blockIdx.x * 128, n0 = blockIdx.y * 128;

    float acc[2][8][4];
    #pragma unroll
    for (int i = 0; i < 2; i++)
        #pragma unroll
        for (int j = 0; j < 8; j++)
            #pragma unroll
            for (int k = 0; k < 4; k++) acc[i][j][k] = 0.f;

    const uint32_t aRow = lane & 15, aCg = (lane >> 4) << 3;
    const uint32_t bRow = (lane & 7) + ((lane >> 4) << 3);
    const uint32_t bCg = ((lane >> 3) & 1) << 3;

    for (int kb = 0; kb < KTOT / 128; kb++) {
        const __half* Ab = A + (size_t)m0 * KTOT + kb * 128;
        #pragma unroll
        for (int i = tid; i < 128 * 16; i += 256) {
            int r = i >> 4, g = i & 15;
            uint4 v = *(const uint4*)(Ab + (size_t)r * KTOT + g * 8);
            *(uint4*)(sA + r * LDS + g * 8) = v;
        }
        const __half* Wb = Wp + (size_t)n0 * KTOT + kb * 128;
        #pragma unroll
        for (int i = tid; i < 128 * 16; i += 256) {
            int r = i >> 4, g = i & 15;
            uint4 v = *(const uint4*)(Wb + (size_t)r * KTOT + g * 8);
            *(uint4*)(sW + r * LDS + g * 8) = v;
        }
        __syncthreads();

        #pragma unroll
        for (int ks = 0; ks < 8; ks++) {
            const int k0 = ks * 16;
            uint32_t afr[2][4];
            #pragma unroll
            for (int mi = 0; mi < 2; mi++) {
                uint32_t addr = sAu + ((wm * 32 + mi * 16 + aRow) * LDS + k0 + aCg) * 2;
                ldsm4(afr[mi], addr);
            }
            uint32_t bfr[8][2];
            #pragma unroll
            for (int nb = 0; nb < 4; nb++) {
                uint32_t addr = sWu + ((wn * 64 + nb * 16 + bRow) * LDS + k0 + bCg) * 2;
                uint32_t t4[4];
                ldsm4(t4, addr);
                bfr[2 * nb][0] = t4[0]; bfr[2 * nb][1] = t4[1];
                bfr[2 * nb + 1][0] = t4[2]; bfr[2 * nb + 1][1] = t4[3];
            }
            #pragma unroll
            for (int mi = 0; mi < 2; mi++)
                #pragma unroll
                for (int ni = 0; ni < 8; ni++)
                    mma16816(acc[mi][ni], afr[mi], bfr[ni]);
        }
        __syncthreads();
    }

    const int lr = lane >> 2, lc = (lane & 3) * 2;
    #pragma unroll
    for (int mi = 0; mi < 2; mi++) {
        #pragma unroll
        for (int rr = 0; rr < 2; rr++) {
            const int row = m0 + wm * 32 + mi * 16 + rr * 8 + lr;
            int win, lloc;
            if (EPI == 3) { win = row / L; lloc = row - win * L; }
            #pragma unroll
            for (int ni = 0; ni < 8; ni++) {
                const int col = n0 + wn * 64 + ni * 8 + lc;
                float v0 = acc[mi][ni][rr * 2 + 0] + __ldg(bias + col);
                float v1 = acc[mi][ni][rr * 2 + 1] + __ldg(bias + col + 1);
                if (EPI == 3) {
                    int s = col >> 7, c = col & 127, head = c >> 5, d = c & 31;
                    __half* dst = (s == 0 ? g_q : (s == 1 ? g_k : g_v)) +
                                  ((size_t)(win * NH + head) * L + lloc) * HD + d;
                    if (s == 0) { v0 *= SCALE; v1 *= SCALE; }
                    *(__half2*)dst = __floats2half2_rn(v0, v1);
                } else if (EPI == 0) {
                    *(__half2*)(g_proj + (size_t)row * Cc + col) = __floats2half2_rn(v0, v1);
                } else if (EPI == 1) {
                    float gg0 = 0.5f * v0 * (1.0f + erff(v0 * 0.7071067811865475f));
                    float gg1 = 0.5f * v1 * (1.0f + erff(v1 * 0.7071067811865475f));
                    *(__half2*)(g_hid + (size_t)row * HID + col) = __floats2half2_rn(gg0, gg1);
                } else {
                    const float2 rv = *(const float2*)(R + (size_t)row * Cc + col);
                    float2 ov; ov.x = v0 + rv.x; ov.y = v1 + rv.y;
                    *(float2*)(Co + (size_t)row * Cc + col) = ov;
                }
            }
        }
    }
}

// ---------------- K3: tensor-core windowed attention -----------------------
// One CTA per (window, head), 4 warps. L=49 padded to 64.
// S = qk^T via mma.m16n8k16 (warp = 16 rows), bias+mask+softmax on fragments,
// P kept in registers (C-frag -> A-frag pack), O = P @ V^T-layout.
constexpr int QP = 40;   // q/k smem row stride (halves): 80B rows, conflict-free
constexpr int VP = 72;   // vT smem row stride: 144B rows, conflict-free
__global__ void __launch_bounds__(128) k_attn(const float* __restrict__ rel_bias) {
    const int w = blockIdx.x, head = blockIdx.y;
    __shared__ __align__(16) __half qs[64 * QP];
    __shared__ __align__(16) __half ks[64 * QP];
    __shared__ __align__(16) __half vT[32 * VP];
    __shared__ float bias_s[256];
    __shared__ int pk[64];
    const int tid = threadIdx.x, warp = tid >> 5, lane = tid & 31;

    const __half* qsrc = g_q + ((size_t)(w * NH + head)) * L * HD;
    const __half* ksrc = g_k + ((size_t)(w * NH + head)) * L * HD;
    const __half* vsrc = g_v + ((size_t)(w * NH + head)) * L * HD;

    // phase 1: zero vT, stage bias table, token tables, load q/k
    for (int i = tid; i < (32 * VP) / 8; i += 128)
        ((uint4*)vT)[i] = make_uint4(0, 0, 0, 0);
    for (int i = tid; i < 256; i += 128)
        bias_s[i] = (i < 169) ? __ldg(rel_bias + i * 4 + head) : 0.f;
    if (tid < 64) {
        int t = tid;
        int rd = t / 7, rm = t - rd * 7;
        int c1 = (rd + 6) * 13 + rm + 6;
        int c2 = rd * 13 + rm;
        int wi = w & 63, wh = wi >> 3, ww = wi & 7;
        int hs = wh * WS + rd, wsp = ww * WS + rm;
        int rh = hs < (Hh - WS) ? 0 : (hs < (Hh - SS) ? 1 : 2);
        int rw = wsp < (Wh - WS) ? 0 : (wsp < (Wh - SS) ? 1 : 2);
        pk[t] = (c1 << 16) | (c2 << 8) | (rh * 3 + rw);
    }
    for (int i = tid; i < 196; i += 128) {   // 49 rows x 4 uint4
        int r = i >> 2, g = i & 3;
        *(uint4*)(qs + r * QP + g * 8) = *(const uint4*)(qsrc + r * 32 + g * 8);
        *(uint4*)(ks + r * QP + g * 8) = *(const uint4*)(ksrc + r * 32 + g * 8);
    }
    __syncthreads();
    // phase 2: V transposed into vT[d][j]
    for (int i = tid; i < 784; i += 128) {   // 49*32/2 half2 elements
        int j = i >> 4, d = (i & 15) * 2;
        __half2 hv = ((const __half2*)vsrc)[i];
        vT[d * VP + j] = __low2half(hv);
        vT[(d + 1) * VP + j] = __high2half(hv);
    }
    __syncthreads();

    // ---- S = q k^T  (warp rows: warp*16 .. +15, cols 0..63) ----
    const uint32_t qsu = smem_u32(qs), ksu = smem_u32(ks), vTu = smem_u32(vT);
    const uint32_t aRow = lane & 15, aCg = (lane >> 4) << 3;
    const uint32_t bRow = (lane & 7) + ((lane >> 4) << 3);
    const uint32_t bCg = ((lane >> 3) & 1) << 3;

    float acc[8][4];
    #pragma unroll
    for (int i = 0; i < 8; i++)
        #pragma unroll
        for (int j = 0; j < 4; j++) acc[i][j] = 0.f;

    uint32_t a0[4], a1[4];
    ldsm4(a0, qsu + ((warp * 16 + aRow) * QP + aCg) * 2);
    ldsm4(a1, qsu + ((warp * 16 + aRow) * QP + 16 + aCg) * 2);
    #pragma unroll
    for (int nt = 0; nt < 4; nt++) {
        uint32_t t4[4];
        ldsm4(t4, ksu + ((nt * 16 + bRow) * QP + bCg) * 2);
        { uint32_t b0[2] = {t4[0], t4[1]}, b1[2] = {t4[2], t4[3]};
          mma16816(acc[2 * nt], a0, b0); mma16816(acc[2 * nt + 1], a0, b1); }
        ldsm4(t4, ksu + ((nt * 16 + bRow) * QP + 16 + bCg) * 2);
        { uint32_t b0[2] = {t4[0], t4[1]}, b1[2] = {t4[2], t4[3]};
          mma16816(acc[2 * nt], a1, b0); mma16816(acc[2 * nt + 1], a1, b1); }
    }

    // ---- bias + mask + softmax on fragments ----
    const int lr = lane >> 2, lc2 = (lane & 3) << 1;
    const int i0 = warp * 16 + lr, i1 = i0 + 8;
    const int pki0 = pk[i0], pki1 = pk[i1];
    const int c1_0 = pki0 >> 16, rg0 = pki0 & 255;
    const int c1_1 = pki1 >> 16, rg1 = pki1 & 255;

    float mx0 = -1e30f, mx1 = -1e30f;
    #pragma unroll
    for (int nb = 0; nb < 8; nb++) {
        #pragma unroll
        for (int jj = 0; jj < 2; jj++) {
            int j = nb * 8 + lc2 + jj;
            int pj = pk[j];
            int c2j = (pj >> 8) & 255, rgj = pj & 255;
            bool jlt = j < L;
            float b0 = bias_s[(c1_0 - c2j) & 255];
            float b1 = bias_s[(c1_1 - c2j) & 255];
            float s0 = acc[nb][jj] + b0 + ((rg0 == rgj) ? 0.f : -100.f);
            float s1 = acc[nb][2 + jj] + b1 + ((rg1 == rgj) ? 0.f : -100.f);
            s0 = jlt ? s0 : -1e30f;
            s1 = jlt ? s1 : -1e30f;
            acc[nb][jj] = s0; acc[nb][2 + jj] = s1;
            mx0 = fmaxf(mx0, s0); mx1 = fmaxf(mx1, s1);
        }
    }
    mx0 = fmaxf(mx0, __shfl_xor_sync(0xffffffffu, mx0, 1));
    mx0 = fmaxf(mx0, __shfl_xor_sync(0xffffffffu, mx0, 2));
    mx1 = fmaxf(mx1, __shfl_xor_sync(0xffffffffu, mx1, 1));
    mx1 = fmaxf(mx1, __shfl_xor_sync(0xffffffffu, mx1, 2));
    float sm0 = 0.f, sm1 = 0.f;
    #pragma unroll
    for (int nb = 0; nb < 8; nb++) {
        #pragma unroll
        for (int jj = 0; jj < 2; jj++) {
            float e0 = __expf(acc[nb][jj] - mx0);
            float e1 = __expf(acc[nb][2 + jj] - mx1);
            acc[nb][jj] = e0; acc[nb][2 + jj] = e1;
            sm0 += e0; sm1 += e1;
        }
    }
    sm0 += __shfl_xor_sync(0xffffffffu, sm0, 1);
    sm0 += __shfl_xor_sync(0xffffffffu, sm0, 2);
    sm1 += __shfl_xor_sync(0xffffffffu, sm1, 1);
    sm1 += __shfl_xor_sync(0xffffffffu, sm1, 2);
    const float inv0 = 1.f / sm0, inv1 = 1.f / sm1;

    // ---- O = P @ V (P from fragments, V^T in smem) ----
    float o[4][4];
    #pragma unroll
    for (int i = 0; i < 4; i++)
        #pragma unroll
        for (int j = 0; j < 4; j++) o[i][j] = 0.f;
    #pragma unroll
    for (int ks2 = 0; ks2 < 4; ks2++) {
        uint32_t pa[4];
        __half2 h;
        h = __floats2half2_rn(acc[2 * ks2][0], acc[2 * ks2][1]);     pa[0] = *(uint32_t*)&h;
        h = __floats2half2_rn(acc[2 * ks2][2], acc[2 * ks2][3]);     pa[1] = *(uint32_t*)&h;
        h = __floats2half2_rn(acc[2 * ks2 + 1][0], acc[2 * ks2 + 1][1]); pa[2] = *(uint32_t*)&h;
        h = __floats2half2_rn(acc[2 * ks2 + 1][2], acc[2 * ks2 + 1][3]); pa[3] = *(uint32_t*)&h;
        uint32_t t4[4];
        ldsm4(t4, vTu + (bRow * VP + ks2 * 16 + bCg) * 2);           // d rows 0-15
        { uint32_t b0[2] = {t4[0], t4[1]}, b1[2] = {t4[2], t4[3]};
          mma16816(o[0], pa, b0); mma16816(o[1], pa, b1); }
        ldsm4(t4, vTu + ((16 + bRow) * VP + ks2 * 16 + bCg) * 2);    // d rows 16-31
        { uint32_t b0[2] = {t4[0], t4[1]}, b1[2] = {t4[2], t4[3]};
          mma16816(o[2], pa, b0); mma16816(o[3], pa, b1); }
    }

    // ---- epilogue: normalize rows, store to window layout ----
    __half* dst = g_att + (size_t)w * L * Cc + head * HD;
    if (i0 < L) {
        #pragma unroll
        for (int nbo = 0; nbo < 4; nbo++) {
            int col = nbo * 8 + lc2;
            __half2 hv = __floats2half2_rn(o[nbo][0] * inv0, o[nbo][1] * inv0);
            *(__half2*)(dst + (size_t)i0 * Cc + col) = hv;
        }
    }
    if (i1 < L) {
        #pragma unroll
        for (int nbo = 0; nbo < 4; nbo++) {
            int col = nbo * 8 + lc2;
            __half2 hv = __floats2half2_rn(o[nbo][2] * inv1, o[nbo][3] * inv1);
            *(__half2*)(dst + (size_t)i1 * Cc + col) = hv;
        }
    }
}

// ---------------- K5: window reverse + unshift + residual + LN2 ------------
__global__ void k_unshift_ln2(const float* __restrict__ x,
                              const float* __restrict__ w2, const float* __restrict__ b2) {
    int gw = (blockIdx.x * blockDim.x + threadIdx.x) >> 5;
    int lane = threadIdx.x & 31;
    if (gw >= MT) return;
    int p = gw;
    int bb = p / (Hh * Wh), pix = p - bb * (Hh * Wh);
    int h = pix / Wh, wc = pix - h * Wh;
    int hs = h - SS; if (hs < 0) hs += Hh;
    int ws = wc - SS; if (ws < 0) ws += Wh;
    int t = (bb * NW + (hs / WS) * 8 + (ws / WS)) * L + (hs % WS) * WS + (ws % WS);
    const __half2* pr = (const __half2*)(g_proj + (size_t)t * Cc);
    float2 p0 = __half22float2(pr[lane * 2]);
    float2 p1 = __half22float2(pr[lane * 2 + 1]);
    float4 xv = ((const float4*)(x + (size_t)p * Cc))[lane];
    float4 x1;
    x1.x = xv.x + p0.x; x1.y = xv.y + p0.y; x1.z = xv.z + p1.x; x1.w = xv.w + p1.y;
    ((float4*)(g_x1 + (size_t)p * Cc))[lane] = x1;
    float s  = x1.x + x1.y + x1.z + x1.w;
    float s2 = x1.x * x1.x + x1.y * x1.y + x1.z * x1.z + x1.w * x1.w;
    s = wsum(s); s2 = wsum(s2);
    float mu = s * (1.f / Cc);
    float var = s2 * (1.f / Cc) - mu * mu;
    float rs = rsqrtf(var + 1e-5f);
    int c = lane * 4;
    float ox = (x1.x - mu) * rs * w2[c + 0] + b2[c + 0];
    float oy = (x1.y - mu) * rs * w2[c + 1] + b2[c + 1];
    float oz = (x1.z - mu) * rs * w2[c + 2] + b2[c + 2];
    float ow = (x1.w - mu) * rs * w2[c + 3] + b2[c + 3];
    __half2* orow = (__half2*)(g_y + (size_t)p * Cc);
    orow[lane * 2]     = __floats2half2_rn(ox, oy);
    orow[lane * 2 + 1] = __floats2half2_rn(oz, ow);
}

// ---------------- launch ----------------
extern "C" void kernel_launch(void* const* d_in, const int* in_sizes, int n_in,
                              void* d_out, int out_size) {
    const float* x      = (const float*)d_in[0];
    const float* n1w    = (const float*)d_in[1];
    const float* n1b    = (const float*)d_in[2];
    const float* qkv_w  = (const float*)d_in[3];
    const float* qkv_b  = (const float*)d_in[4];
    const float* proj_w = (const float*)d_in[5];
    const float* proj_b = (const float*)d_in[6];
    const float* rel_b  = (const float*)d_in[7];
    const float* n2w    = (const float*)d_in[8];
    const float* n2b    = (const float*)d_in[9];
    const float* fc1_w  = (const float*)d_in[10];
    const float* fc1_b  = (const float*)d_in[11];
    const float* fc2_w  = (const float*)d_in[12];
    const float* fc2_b  = (const float*)d_in[13];
    float* out = (float*)d_out;

    __half *p_hwin, *p_att, *p_y, *p_hid, *p_wqkv, *p_wproj, *p_wfc1, *p_wfc2;
    float* p_x1;
    cudaGetSymbolAddress((void**)&p_hwin, g_hwin);
    cudaGetSymbolAddress((void**)&p_att,  g_att);
    cudaGetSymbolAddress((void**)&p_y,    g_y);
    cudaGetSymbolAddress((void**)&p_hid,  g_hid);
    cudaGetSymbolAddress((void**)&p_x1,   g_x1);
    cudaGetSymbolAddress((void**)&p_wqkv, g_wqkv);
    cudaGetSymbolAddress((void**)&p_wproj, g_wproj);
    cudaGetSymbolAddress((void**)&p_wfc1, g_wfc1);
    cudaGetSymbolAddress((void**)&p_wfc2, g_wfc2);

    constexpr int SMB = 2 * 128 * LDS * 2;  // 69632 bytes
    cudaFuncSetAttribute(k_hmma<384, 128, 3>, cudaFuncAttributeMaxDynamicSharedMemorySize, SMB);
    cudaFuncSetAttribute(k_hmma<128, 128, 0>, cudaFuncAttributeMaxDynamicSharedMemorySize, SMB);
    cudaFuncSetAttribute(k_hmma<512, 128, 1>, cudaFuncAttributeMaxDynamicSharedMemorySize, SMB);
    cudaFuncSetAttribute(k_hmma<128, 512, 2>, cudaFuncAttributeMaxDynamicSharedMemorySize, SMB);

    const int GM = MT / 128;  // 1568 M-tiles

    k_cvt<<<256, 256>>>(qkv_w, proj_w, fc1_w, fc2_w);
    k_ln1<<<MT / 8, 256>>>(x, n1w, n1b);
    k_hmma<384, 128, 3><<<dim3(GM, 3), 256, SMB>>>(p_hwin, p_wqkv, qkv_b, nullptr, nullptr);
    k_attn<<<dim3(Bz * NW, NH), 128>>>(rel_b);
    k_hmma<128, 128, 0><<<dim3(GM, 1), 256, SMB>>>(p_att, p_wproj, proj_b, nullptr, nullptr);
    k_unshift_ln2<<<MT / 8, 256>>>(x, n2w, n2b);
    k_hmma<512, 128, 1><<<dim3(GM, 4), 256, SMB>>>(p_y, p_wfc1, fc1_b, nullptr, nullptr);
    k_hmma<128, 512, 2><<<dim3(GM, 1), 256, SMB>>>(p_hid, p_wfc2, fc2_b, p_x1, out);
}